// round 13
// baseline (speedup 1.0000x reference)
#include <cuda_runtime.h>
#include <cuda_bf16.h>

#define TT 512
#define MM 16
#define MQ 4            // m rows per warp unit
#define PP 600
#define BB 32
#define PW 32
#define NPT 19
#define UNITS (BB * NPT * 4)            // 2432 warp units
#define WPB 9
#define NBLK ((UNITS + WPB - 1) / WPB)  // 271 blocks -> <=2 per SM
#define TH 256          // t-half length
#define CH 64           // gather/mma chunk

typedef unsigned long long ull;

__device__ __forceinline__ float ex2(float v) {
    float r;
    asm("ex2.approx.ftz.f32 %0, %1;" : "=f"(r) : "f"(v));
    return r;
}
__device__ __forceinline__ ull pack2(float lo, float hi) {
    ull r;
    asm("mov.b64 %0, {%1, %2};" : "=l"(r) : "f"(lo), "f"(hi));
    return r;
}
__device__ __forceinline__ void unpack2(ull v, float& lo, float& hi) {
    asm("mov.b64 {%0, %1}, %2;" : "=f"(lo), "=f"(hi) : "l"(v));
}
__device__ __forceinline__ ull fma2(ull a, ull b, ull c) {
    ull d;
    asm("fma.rn.f32x2 %0, %1, %2, %3;" : "=l"(d) : "l"(a), "l"(b), "l"(c));
    return d;
}

// Per-warp smem slice (floats): sxc[256] | sidx[256] (int) | sky[MQ][CH] float2
#define SLICE (TH + TH + MQ * CH * 2)   // 1024 floats = 4 KB
// Block = 9 warps -> 36 KB. No __syncthreads anywhere; warps fully autonomous.

template<bool EQ>
__device__ __forceinline__ void chunk_mma(
    const float* sxc, const float2* sky, int c0, int cend,
    float v, float r0, float r1, ull* __restrict__ acc)
{
    for (int jj = c0; jj < cend; jj += 2) {
        float2 xv = *(const float2*)(sxc + jj);        // LDS.64 broadcast
        float d0 = v - xv.x, d1 = v - xv.y;
        float e0 = d0 * (-d0), e1 = d1 * (-d1);

        ull wp0, wp1;
        if (EQ) {
            float w0 = ex2(e0), w1 = ex2(e1);
            wp0 = pack2(w0, w0);
            wp1 = pack2(w1, w1);
        } else {
            wp0 = pack2(ex2(e0 * r0), ex2(e0 * r1));
            wp1 = pack2(ex2(e1 * r0), ex2(e1 * r1));
        }

        const int jl = jj - c0;
        #pragma unroll
        for (int m = 0; m < MQ; m++) {
            ulonglong2 q = *(const ulonglong2*)(sky + m * CH + jl); // LDS.128
            acc[m] = fma2(q.y, wp1, fma2(q.x, wp0, acc[m]));
        }
    }
}

__global__ __launch_bounds__(WPB * 32) void func_repr_kernel(
    const float* __restrict__ y, const float* __restrict__ x,
    const int*   __restrict__ mask, const float* __restrict__ sigma,
    float* __restrict__ out)
{
    extern __shared__ float sm[];
    const int tid  = threadIdx.x;
    const int lane = tid & 31;
    const int w    = tid >> 5;

    const int unit = blockIdx.x * WPB + w;
    if (unit >= UNITS) return;                 // warp-level exit; no barriers

    const int quarter = unit & 3;
    const int bt      = unit >> 2;
    const int b       = bt / NPT;
    const int tile    = bt % NPT;

    float*  sxc  = sm + w * SLICE;
    int*    sidx = (int*)(sxc + TH);
    float2* sky  = (float2*)(sxc + 2 * TH);

    const float s0 = sigma[0], s1 = sigma[1];
    const float LOG2E = 1.4426950408889634f;
    const float smax  = fmaxf(s0, s1);
    const float rcmin = sqrtf(0.5f * LOG2E) / smax;     // sqrt(c_min)
    const float r0 = (smax / s0) * (smax / s0);
    const float r1 = (smax / s1) * (smax / s1);

    const int   pfirst = tile * PW;
    const float gA = fmaf((float)pfirst,            50.0f / 599.0f, -1.0f);
    const float gZ = fmaf((float)(pfirst + PW - 1), 50.0f / 599.0f, -1.0f);
    const float vlo = rcmin * gA - 6.7f;   // dropped weight <= 2^-44.9
    const float vhi = rcmin * gZ + 6.7f;

    const int   p = pfirst + lane;
    const float v = rcmin * fmaf((float)p, 50.0f / 599.0f, -1.0f);

    ull acc[MQ];
    #pragma unroll
    for (int m = 0; m < MQ; m++) acc[m] = 0ULL;

    const float* xr = x + (size_t)b * TT;
    const float* yb = y    + ((size_t)b * MM + quarter * MQ) * TT;
    const int*   mb = mask + ((size_t)b * MM + quarter * MQ) * TT;
    const unsigned lmlt = (1u << lane) - 1u;
    const bool eq = (s0 == s1);

    #pragma unroll
    for (int half = 0; half < 2; half++) {
        const int t0 = half * TH;

        // ---- warp-private ballot compaction of this t-half ----
        int base = 0;
        #pragma unroll
        for (int r = 0; r < TH / 32; r++) {
            float xs = xr[t0 + r * 32 + lane] * rcmin;
            bool in = (xs >= vlo) & (xs <= vhi);
            unsigned msk = __ballot_sync(0xFFFFFFFFu, in);
            if (in) {
                int pos = base + __popc(msk & lmlt);
                sxc[pos]  = xs;
                sidx[pos] = t0 + r * 32 + lane;
            }
            base += __popc(msk);
        }
        const int K = base;
        int Kp = K;
        if (K & 1) {
            if (lane == 0 && K < TH) sxc[K] = 1.0e9f;  // sentinel -> weight 0
            Kp = K + 1;
        }
        __syncwarp();

        // ---- chunked private gather + mma (typical K~28: one chunk) ----
        for (int c0 = 0; c0 < Kp; c0 += CH) {
            const int cend = min(c0 + CH, Kp);

            for (int j = c0 + lane; j < cend; j += 32) {
                if (j < K) {
                    int t = sidx[j];
                    #pragma unroll
                    for (int m = 0; m < MQ; m++)
                        sky[m * CH + (j - c0)] =
                            make_float2((float)__ldg(mb + m * TT + t),
                                        __ldg(yb + m * TT + t));
                } else {
                    #pragma unroll
                    for (int m = 0; m < MQ; m++)
                        sky[m * CH + (j - c0)] = make_float2(0.f, 0.f);
                }
            }
            __syncwarp();

            if (eq)
                chunk_mma<true >(sxc, sky, c0, cend, v, r0, r1, acc);
            else
                chunk_mma<false>(sxc, sky, c0, cend, v, r0, r1, acc);
            __syncwarp();
        }
    }

    // ---- epilogue: lane owns p completely; no reduction ----
    if (p < PP) {
        float4* op = (float4*)(out + ((size_t)b * PP + p) * (2 * MM)
                               + quarter * 2 * MQ);
        #pragma unroll
        for (int m = 0; m < MQ; m += 2) {
            float dA, cA, dB, cB;
            unpack2(acc[m],     dA, cA);
            unpack2(acc[m + 1], dB, cB);
            op[m >> 1] = make_float4(dA, __fdividef(cA, dA + 1e-8f),
                                     dB, __fdividef(cB, dB + 1e-8f));
        }
    }
}

extern "C" void kernel_launch(void* const* d_in, const int* in_sizes, int n_in,
                              void* d_out, int out_size) {
    const float* y     = (const float*)d_in[0];
    const float* x     = (const float*)d_in[1];
    const int*   mask  = (const int*)  d_in[2];
    const float* sigma = (const float*)d_in[3];
    float*       out   = (float*)d_out;

    const size_t smem = (size_t)WPB * SLICE * sizeof(float);   // 36 KB
    cudaFuncSetAttribute(func_repr_kernel,
                         cudaFuncAttributeMaxDynamicSharedMemorySize, (int)smem);

    func_repr_kernel<<<NBLK, WPB * 32, smem>>>(y, x, mask, sigma, out);
}